// round 10
// baseline (speedup 1.0000x reference)
#include <cuda_runtime.h>
#include <cstdint>

#define D       128
#define NROWS   20000
#define NPAD    20480
#define NA      1024
#define TA      8         // anchors per CTA
#define CROWS   1024
#define NCHUNK  20
#define KSEL    8
#define KTOP    10
#define GAMMA   1.0f
#define SCALE   25.4f     // int8 quant scale, selection-only
#define QB      79        // quant row-blocks (79*256 >= 20000)

typedef unsigned int uint;

// Static device scratch (allocation-free rule: __device__ globals only)
__device__ __align__(16) uint g_qT[2][D / 4][NPAD];     // transposed packed DB
__device__ __align__(16) uint g_anchq[2][NA][D / 4];    // packed quantized anchors
__device__ __align__(16) float g_anch[2][NA][D];        // fp32 anchors
__device__ float g_Dm[NA];                              // positive dist + gamma
__device__ int   g_candi[2][NA][NCHUNK * KSEL];         // candidate row indices
__device__ float g_partial[2 * NA];                     // per-anchor loss

// Fused SAD-accumulate: acc += sum_bytes(|s8(a) - s8(b)|)  (single SASS op)
__device__ __forceinline__ void sad4(uint& acc, uint a, uint b) {
    asm("vabsdiff4.u32.s32.s32.add %0, %1, %2, %0;" : "+r"(acc) : "r"(a), "r"(b));
}

__device__ __forceinline__ uint quant_pack4(float4 f) {
    int x = __float2int_rn(fminf(fmaxf(f.x * SCALE, -127.f), 127.f));
    int y = __float2int_rn(fminf(fmaxf(f.y * SCALE, -127.f), 127.f));
    int z = __float2int_rn(fminf(fmaxf(f.z * SCALE, -127.f), 127.f));
    int w = __float2int_rn(fminf(fmaxf(f.w * SCALE, -127.f), 127.f));
    return (uint)(x & 255) | ((uint)(y & 255) << 8) |
           ((uint)(z & 255) << 16) | ((uint)(w & 255) << 24);
}

// ---------------------------------------------------------------------------
// Prep: quantize+transpose DBs (blocks 0..2*QB-1) and gather anchors.
// ---------------------------------------------------------------------------
__global__ void k_prep(const float* __restrict__ out1,
                       const float* __restrict__ out2,
                       const int* __restrict__ an1,
                       const int* __restrict__ an2) {
    int b = blockIdx.x;
    int tid = threadIdx.x;
    if (b < 2 * QB) {
        int side = (b >= QB);
        const float* src = side ? out1 : out2;
        int row = (side ? b - QB : b) * 256 + tid;
        if (row >= NROWS) return;
        const float4* s = (const float4*)(src + (size_t)row * D);
        #pragma unroll
        for (int j = 0; j < D / 4; j++)
            g_qT[side][j][row] = quant_pack4(s[j]);
        return;
    }
    // gather: 2 anchors per block, 128 threads each
    int i = (b - 2 * QB) * 2 + (tid >> 7);
    int d = tid & 127;
    float v1 = out1[(size_t)an1[i] * D + d];
    float v2 = out2[(size_t)an2[i] * D + d];
    g_anch[0][i][d] = v1;
    g_anch[1][i][d] = v2;
    int q1 = __float2int_rn(fminf(fmaxf(v1 * SCALE, -127.f), 127.f)) & 255;
    int q2 = __float2int_rn(fminf(fmaxf(v2 * SCALE, -127.f), 127.f)) & 255;
    __shared__ unsigned char b1[2][D], b2[2][D];
    int h = tid >> 7;
    b1[h][d] = (unsigned char)q1;
    b2[h][d] = (unsigned char)q2;
    __syncthreads();
    if (d < D / 4) {
        g_anchq[0][i][d] = ((const uint*)b1[h])[d];
        g_anchq[1][i][d] = ((const uint*)b2[h])[d];
    }
    float x = fabsf(v1 - v2);
    #pragma unroll
    for (int off = 16; off; off >>= 1) x += __shfl_down_sync(0xffffffffu, x, off);
    __shared__ float ws[8];
    if ((tid & 31) == 0) ws[tid >> 5] = x;
    __syncthreads();
    if (d == 0) g_Dm[i] = ws[4 * h] + ws[4 * h + 1] + ws[4 * h + 2] + ws[4 * h + 3] + GAMMA;
}

// ---------------------------------------------------------------------------
// int8 SAD distances + register-resident tournament top-8.
// Grid (128 tiles, 20 chunks, 2 sides), 512 threads, 2 CTAs/SM.
// Mainloop identical to round-6 (proven). Selection: stage 1 per-warp top-8
// of its own 128-row slice (values already in regs), stage 2 merges 8 slices.
// smem: 3 KB (vs 33 KB) -> L1D keeps the hot DB chunks resident.
// ---------------------------------------------------------------------------
__global__ void __launch_bounds__(512, 2) k_dist() {
    int tile  = blockIdx.x;
    int chunk = blockIdx.y;
    int side  = blockIdx.z;
    int tid = threadIdx.x;
    int half = tid >> 8;          // anchor group: 0 -> anchors 0-3, 1 -> 4-7
    int pos  = tid & 255;

    __shared__ __align__(16) uint sh_aq[TA][D / 4];  // 1 KB
    __shared__ int sh_cand[TA][8][KSEL];             // 2 KB slice candidates

    if (tid < TA * (D / 4)) {
        int t = tid >> 5, j = tid & 31;
        sh_aq[t][j] = g_anchq[side][tile * TA + t][j];
    }
    __syncthreads();

    uint acc[4][4];
    #pragma unroll
    for (int t = 0; t < 4; t++)
        #pragma unroll
        for (int r = 0; r < 4; r++) acc[t][r] = 0;

    const int p2 = 2 * pos;       // local rows p2, p2+1, p2+512, p2+513
    const uint* __restrict__ qp = &g_qT[side][0][0] + chunk * CROWS + p2;
    const int ta0 = half * 4;

    #pragma unroll
    for (int jb = 0; jb < 8; jb++) {
        uint4 a0 = *(const uint4*)&sh_aq[ta0 + 0][4 * jb];
        uint4 a1 = *(const uint4*)&sh_aq[ta0 + 1][4 * jb];
        uint4 a2 = *(const uint4*)&sh_aq[ta0 + 2][4 * jb];
        uint4 a3 = *(const uint4*)&sh_aq[ta0 + 3][4 * jb];
        #pragma unroll
        for (int jj = 0; jj < 4; jj++) {
            int j = 4 * jb + jj;
            uint2 bA = *(const uint2*)(qp + (size_t)j * NPAD);        // rows p2,p2+1
            uint2 bB = *(const uint2*)(qp + (size_t)j * NPAD + 512);  // +512,+513
            uint av0 = jj == 0 ? a0.x : jj == 1 ? a0.y : jj == 2 ? a0.z : a0.w;
            uint av1 = jj == 0 ? a1.x : jj == 1 ? a1.y : jj == 2 ? a1.z : a1.w;
            uint av2 = jj == 0 ? a2.x : jj == 1 ? a2.y : jj == 2 ? a2.z : a2.w;
            uint av3 = jj == 0 ? a3.x : jj == 1 ? a3.y : jj == 2 ? a3.z : a3.w;
            sad4(acc[0][0], av0, bA.x);
            sad4(acc[0][1], av0, bA.y);
            sad4(acc[0][2], av0, bB.x);
            sad4(acc[0][3], av0, bB.y);
            sad4(acc[1][0], av1, bA.x);
            sad4(acc[1][1], av1, bA.y);
            sad4(acc[1][2], av1, bB.x);
            sad4(acc[1][3], av1, bB.y);
            sad4(acc[2][0], av2, bA.x);
            sad4(acc[2][1], av2, bA.y);
            sad4(acc[2][2], av2, bB.x);
            sad4(acc[2][3], av2, bB.y);
            sad4(acc[3][0], av3, bA.x);
            sad4(acc[3][1], av3, bA.y);
            sad4(acc[3][2], av3, bB.x);
            sad4(acc[3][3], av3, bB.y);
        }
    }

    // Pack in place: (sad<<10 | local_idx); invalid rows -> INT_MAX.
    const int nb = chunk * CROWS;
    #pragma unroll
    for (int t = 0; t < 4; t++) {
        #pragma unroll
        for (int r = 0; r < 4; r++) {
            int idx = (r & 1) + ((r >> 1) << 9) + p2;   // p2,p2+1,p2+512,p2+513
            acc[t][r] = (nb + idx < NROWS) ? ((acc[t][r] << 10) | (uint)idx)
                                           : 0x7fffffffu;
        }
    }

    int w = tid >> 5, lane = tid & 31;
    int wslice = w & 7;   // this warp's 128-row slice id within its half

    // Stage 1: per-warp top-8 of each of its 4 anchors (values in regs).
    #pragma unroll
    for (int t = 0; t < 4; t++) {
        #pragma unroll 1
        for (int it = 0; it < KSEL; it++) {
            uint m = min(min(acc[t][0], acc[t][1]), min(acc[t][2], acc[t][3]));
            m = __reduce_min_sync(0xffffffffu, m);
            if (lane == 0) sh_cand[ta0 + t][wslice][it] = (int)m;
            int idx = (int)(m & 1023u);
            if (((idx >> 1) & 31) == lane) {   // owner lane invalidates its copy
                int r = (idx & 1) | ((idx >> 8) & 2);
                if      (r == 0) acc[t][0] = 0x7fffffffu;
                else if (r == 1) acc[t][1] = 0x7fffffffu;
                else if (r == 2) acc[t][2] = 0x7fffffffu;
                else             acc[t][3] = 0x7fffffffu;
            }
        }
    }
    __syncthreads();

    // Stage 2: warp w (0..7) merges anchor w's 8x8 slice candidates -> top-8.
    if (w < TA) {
        const int* c = &sh_cand[w][0][0];   // 64 ints
        uint v0 = (uint)c[lane];
        uint v1 = (uint)c[lane + 32];
        int aglob = tile * TA + w;
        #pragma unroll 1
        for (int it = 0; it < KSEL; it++) {
            uint m = __reduce_min_sync(0xffffffffu, min(v0, v1));
            if (lane == 0)
                g_candi[side][aglob][chunk * KSEL + it] = nb + (int)(m & 1023u);
            if (v0 == m)      v0 = 0x7fffffffu;   // packed values unique (idx)
            else if (v1 == m) v1 = 0x7fffffffu;
        }
    }
}

// ---------------------------------------------------------------------------
// Exact fp32 repair: one THREAD per candidate (high MLP), then warp-0 top-10.
// ---------------------------------------------------------------------------
#define NCAND (NCHUNK * KSEL)   // 160
__global__ void __launch_bounds__(256) k_exact(const float* __restrict__ out1,
                                               const float* __restrict__ out2) {
    int a = blockIdx.x;               // 0..2047
    int side = a >> 10, ai = a & (NA - 1);
    int tid = threadIdx.x, lane = tid & 31;
    __shared__ __align__(16) float4 sh_a4[D / 4];
    __shared__ float sh_dv[NCAND];

    if (tid < D / 4) sh_a4[tid] = ((const float4*)g_anch[side][ai])[tid];
    __syncthreads();

    if (tid < NCAND) {
        int ix = g_candi[side][ai][tid];
        const float* db = side ? out1 : out2;
        const float4* rp = (const float4*)(db + (size_t)ix * D);
        float s0 = 0.f, s1 = 0.f, s2 = 0.f, s3 = 0.f;
        #pragma unroll 8
        for (int j = 0; j < D / 4; j++) {
            float4 bv = rp[j];
            float4 av = sh_a4[j];
            s0 += fabsf(av.x - bv.x);
            s1 += fabsf(av.y - bv.y);
            s2 += fabsf(av.z - bv.z);
            s3 += fabsf(av.w - bv.w);
        }
        sh_dv[tid] = (s0 + s1) + (s2 + s3);
    }
    __syncthreads();

    if (tid < 32) {
        // lane holds 5 values (stride 32); nonneg floats order as uint bits.
        float v[5];
        #pragma unroll
        for (int k = 0; k < 5; k++) v[k] = sh_dv[lane + 32 * k];
        const float INF = __int_as_float(0x7f800000);
        float Dm = g_Dm[ai];
        float loss = 0.0f;
        #pragma unroll 1
        for (int it = 0; it < KTOP; it++) {
            uint mb = 0xffffffffu;
            #pragma unroll
            for (int k = 0; k < 5; k++) mb = min(mb, __float_as_uint(v[k]));
            mb = __reduce_min_sync(0xffffffffu, mb);
            float m = __uint_as_float(mb);
            loss += fmaxf(0.0f, Dm - m);
            // remove exactly one copy of m (ballot-elected leader lane)
            bool have = (v[0] == m) | (v[1] == m) | (v[2] == m) |
                        (v[3] == m) | (v[4] == m);
            uint msk = __ballot_sync(0xffffffffu, have);
            if (lane == (int)(__ffs(msk) - 1)) {
                if      (v[0] == m) v[0] = INF;
                else if (v[1] == m) v[1] = INF;
                else if (v[2] == m) v[2] = INF;
                else if (v[3] == m) v[3] = INF;
                else                v[4] = INF;
            }
        }
        if (lane == 0) g_partial[a] = loss;
    }
}

// ---------------------------------------------------------------------------
// Deterministic final reduction: 2048 partials -> scalar / (A*K)
// ---------------------------------------------------------------------------
__global__ void k_final(float* __restrict__ out) {
    __shared__ float s[512];
    int tid = threadIdx.x;   // 1024 threads; 512 float4 elements total
    float v = 0.0f;
    if (tid < 512) {
        float4 p = ((const float4*)g_partial)[tid];
        v = (p.x + p.y) + (p.z + p.w);
        s[tid] = v;
    }
    __syncthreads();
    for (int st = 256; st; st >>= 1) {
        if (tid < st) s[tid] += s[tid + st];
        __syncthreads();
    }
    if (tid == 0) out[0] = s[0] / (float)(NA * KTOP);
}

// ---------------------------------------------------------------------------
extern "C" void kernel_launch(void* const* d_in, const int* in_sizes, int n_in,
                              void* d_out, int out_size) {
    const float* out1 = (const float*)d_in[0];
    const float* out2 = (const float*)d_in[1];
    const int*   an1  = (const int*)d_in[2];
    const int*   an2  = (const int*)d_in[3];
    float* out = (float*)d_out;

    k_prep<<<2 * QB + NA / 2, 256>>>(out1, out2, an1, an2);
    k_dist<<<dim3(NA / TA, NCHUNK, 2), 512>>>();
    k_exact<<<2 * NA, 256>>>(out1, out2);
    k_final<<<1, 1024>>>(out);
}

// round 11
// speedup vs baseline: 1.8800x; 1.8800x over previous
#include <cuda_runtime.h>
#include <cstdint>

#define D       128
#define NROWS   20000
#define NPAD    20480
#define NA      1024
#define TA      8         // anchors per CTA
#define CROWS   1024
#define NCHUNK  20
#define KSEL    8
#define KTOP    10
#define GAMMA   1.0f
#define SCALE   25.4f     // int8 quant scale, selection-only
#define QB      79        // quant row-blocks (79*256 >= 20000)

typedef unsigned int uint;

// Static device scratch (allocation-free rule: __device__ globals only)
__device__ __align__(16) uint g_qT[2][D / 4][NPAD];     // transposed packed DB
__device__ __align__(16) uint g_anchq[2][NA][D / 4];    // packed quantized anchors
__device__ __align__(16) float g_anch[2][NA][D];        // fp32 anchors
__device__ float g_Dm[NA];                              // positive dist + gamma
__device__ int   g_candi[2][NA][NCHUNK * KSEL];         // candidate row indices
__device__ float g_partial[2 * NA];                     // per-anchor loss

// Fused SAD-accumulate: acc += sum_bytes(|s8(a) - s8(b)|)  (single SASS op)
__device__ __forceinline__ void sad4(uint& acc, uint a, uint b) {
    asm("vabsdiff4.u32.s32.s32.add %0, %1, %2, %0;" : "+r"(acc) : "r"(a), "r"(b));
}

__device__ __forceinline__ uint quant_pack4(float4 f) {
    int x = __float2int_rn(fminf(fmaxf(f.x * SCALE, -127.f), 127.f));
    int y = __float2int_rn(fminf(fmaxf(f.y * SCALE, -127.f), 127.f));
    int z = __float2int_rn(fminf(fmaxf(f.z * SCALE, -127.f), 127.f));
    int w = __float2int_rn(fminf(fmaxf(f.w * SCALE, -127.f), 127.f));
    return (uint)(x & 255) | ((uint)(y & 255) << 8) |
           ((uint)(z & 255) << 16) | ((uint)(w & 255) << 24);
}

// ---------------------------------------------------------------------------
// Prep: quantize+transpose DBs (blocks 0..2*QB-1) and gather anchors.
// ---------------------------------------------------------------------------
__global__ void k_prep(const float* __restrict__ out1,
                       const float* __restrict__ out2,
                       const int* __restrict__ an1,
                       const int* __restrict__ an2) {
    int b = blockIdx.x;
    int tid = threadIdx.x;
    if (b < 2 * QB) {
        int side = (b >= QB);
        const float* src = side ? out1 : out2;
        int row = (side ? b - QB : b) * 256 + tid;
        if (row >= NROWS) return;
        const float4* s = (const float4*)(src + (size_t)row * D);
        #pragma unroll
        for (int j = 0; j < D / 4; j++)
            g_qT[side][j][row] = quant_pack4(s[j]);
        return;
    }
    // gather: 2 anchors per block, 128 threads each
    int i = (b - 2 * QB) * 2 + (tid >> 7);
    int d = tid & 127;
    float v1 = out1[(size_t)an1[i] * D + d];
    float v2 = out2[(size_t)an2[i] * D + d];
    g_anch[0][i][d] = v1;
    g_anch[1][i][d] = v2;
    int q1 = __float2int_rn(fminf(fmaxf(v1 * SCALE, -127.f), 127.f)) & 255;
    int q2 = __float2int_rn(fminf(fmaxf(v2 * SCALE, -127.f), 127.f)) & 255;
    __shared__ unsigned char b1[2][D], b2[2][D];
    int h = tid >> 7;
    b1[h][d] = (unsigned char)q1;
    b2[h][d] = (unsigned char)q2;
    __syncthreads();
    if (d < D / 4) {
        g_anchq[0][i][d] = ((const uint*)b1[h])[d];
        g_anchq[1][i][d] = ((const uint*)b2[h])[d];
    }
    float x = fabsf(v1 - v2);
    #pragma unroll
    for (int off = 16; off; off >>= 1) x += __shfl_down_sync(0xffffffffu, x, off);
    __shared__ float ws[8];
    if ((tid & 31) == 0) ws[tid >> 5] = x;
    __syncthreads();
    if (d == 0) g_Dm[i] = ws[4 * h] + ws[4 * h + 1] + ws[4 * h + 2] + ws[4 * h + 3] + GAMMA;
}

// ---------------------------------------------------------------------------
// int8 SAD distances + per-chunk top-8 selection (two-stage, 16 warps).
// Grid (128 tiles, 20 chunks, 2 sides), 512 threads, 2 CTAs/SM.
// Mainloop identical to the proven round-6 kernel; accs die at the smem store
// (no liveness across selection -> no spill risk).
// ---------------------------------------------------------------------------
__global__ void __launch_bounds__(512, 2) k_dist() {
    int tile  = blockIdx.x;
    int chunk = blockIdx.y;
    int side  = blockIdx.z;
    int tid = threadIdx.x;
    int half = tid >> 8;          // anchor group: 0 -> anchors 0-3, 1 -> 4-7
    int pos  = tid & 255;

    __shared__ __align__(16) uint sh_aq[TA][D / 4];  // 1 KB
    __shared__ __align__(16) int sh_dist[TA][CROWS]; // 32 KB packed dists
    __shared__ int sh_cand[TA][2][KSEL];             // stage-1 candidates

    if (tid < TA * (D / 4)) {
        int t = tid >> 5, j = tid & 31;
        sh_aq[t][j] = g_anchq[side][tile * TA + t][j];
    }
    __syncthreads();

    uint acc[4][4];
    #pragma unroll
    for (int t = 0; t < 4; t++)
        #pragma unroll
        for (int r = 0; r < 4; r++) acc[t][r] = 0;

    const int p2 = 2 * pos;       // local rows p2, p2+1, p2+512, p2+513
    const uint* __restrict__ qp = &g_qT[side][0][0] + chunk * CROWS + p2;
    const int ta0 = half * 4;

    #pragma unroll
    for (int jb = 0; jb < 8; jb++) {
        uint4 a0 = *(const uint4*)&sh_aq[ta0 + 0][4 * jb];
        uint4 a1 = *(const uint4*)&sh_aq[ta0 + 1][4 * jb];
        uint4 a2 = *(const uint4*)&sh_aq[ta0 + 2][4 * jb];
        uint4 a3 = *(const uint4*)&sh_aq[ta0 + 3][4 * jb];
        #pragma unroll
        for (int jj = 0; jj < 4; jj++) {
            int j = 4 * jb + jj;
            uint2 bA = *(const uint2*)(qp + (size_t)j * NPAD);        // rows p2,p2+1
            uint2 bB = *(const uint2*)(qp + (size_t)j * NPAD + 512);  // +512,+513
            uint av0 = jj == 0 ? a0.x : jj == 1 ? a0.y : jj == 2 ? a0.z : a0.w;
            uint av1 = jj == 0 ? a1.x : jj == 1 ? a1.y : jj == 2 ? a1.z : a1.w;
            uint av2 = jj == 0 ? a2.x : jj == 1 ? a2.y : jj == 2 ? a2.z : a2.w;
            uint av3 = jj == 0 ? a3.x : jj == 1 ? a3.y : jj == 2 ? a3.z : a3.w;
            sad4(acc[0][0], av0, bA.x);
            sad4(acc[0][1], av0, bA.y);
            sad4(acc[0][2], av0, bB.x);
            sad4(acc[0][3], av0, bB.y);
            sad4(acc[1][0], av1, bA.x);
            sad4(acc[1][1], av1, bA.y);
            sad4(acc[1][2], av1, bB.x);
            sad4(acc[1][3], av1, bB.y);
            sad4(acc[2][0], av2, bA.x);
            sad4(acc[2][1], av2, bA.y);
            sad4(acc[2][2], av2, bB.x);
            sad4(acc[2][3], av2, bB.y);
            sad4(acc[3][0], av3, bA.x);
            sad4(acc[3][1], av3, bA.y);
            sad4(acc[3][2], av3, bB.x);
            sad4(acc[3][3], av3, bB.y);
        }
    }

    // Store packed (sad<<10 | idx); invalid rows -> INT_MAX.
    const int nb = chunk * CROWS;
    #pragma unroll
    for (int r = 0; r < 4; r++) {
        int idx = (r & 1) + ((r >> 1) << 9) + p2;   // p2, p2+1, p2+512, p2+513
        bool valid = (nb + idx) < NROWS;
        #pragma unroll
        for (int t = 0; t < 4; t++) {
            int v = valid ? (int)((acc[t][r] << 10) | (uint)idx) : 0x7fffffff;
            sh_dist[ta0 + t][idx] = v;
        }
    }
    __syncthreads();

    int w = tid >> 5, lane = tid & 31;

    // Stage 1: warp w -> anchor (w&7), row-half (w>>3). Top-8 of 512 values.
    {
        int t = w & 7, hh = w >> 3;
        int* rowp = &sh_dist[t][hh * 512];
        #pragma unroll 1
        for (int it = 0; it < KSEL; it++) {
            int m = 0x7fffffff;
            #pragma unroll
            for (int k = 0; k < 4; k++) {
                int4 v = *(const int4*)&rowp[4 * lane + 128 * k];
                m = min(m, min(min(v.x, v.y), min(v.z, v.w)));
            }
            m = (int)__reduce_min_sync(0xffffffffu, (uint)m);
            if (lane == 0) sh_cand[t][hh][it] = m;
            int idx = m & 1023;                    // global local-row idx
            int loc = idx - hh * 512;              // offset within this half
            if (((loc >> 2) & 31) == lane) rowp[loc] = 0x7fffffff;
            __syncwarp();
        }
    }
    __syncthreads();

    // Stage 2: warps 0-7 merge the 16 candidates of anchor w -> final top-8.
    if (w < TA) {
        uint v = (lane < 2 * KSEL) ? (uint)sh_cand[w][lane >> 3][lane & 7]
                                   : 0xffffffffu;
        int aglob = tile * TA + w;
        #pragma unroll 1
        for (int it = 0; it < KSEL; it++) {
            uint m = __reduce_min_sync(0xffffffffu, v);
            if (lane == 0)
                g_candi[side][aglob][chunk * KSEL + it] = nb + (int)(m & 1023u);
            if (v == m) v = 0xffffffffu;   // packed values unique (idx bits)
        }
    }
}

// ---------------------------------------------------------------------------
// Exact fp32 repair: one THREAD per candidate (high MLP), then warp-0 top-10.
// ---------------------------------------------------------------------------
#define NCAND (NCHUNK * KSEL)   // 160
__global__ void __launch_bounds__(256) k_exact(const float* __restrict__ out1,
                                               const float* __restrict__ out2) {
    int a = blockIdx.x;               // 0..2047
    int side = a >> 10, ai = a & (NA - 1);
    int tid = threadIdx.x, lane = tid & 31;
    __shared__ __align__(16) float4 sh_a4[D / 4];
    __shared__ float sh_dv[NCAND];

    if (tid < D / 4) sh_a4[tid] = ((const float4*)g_anch[side][ai])[tid];
    __syncthreads();

    if (tid < NCAND) {
        int ix = g_candi[side][ai][tid];
        const float* db = side ? out1 : out2;
        const float4* rp = (const float4*)(db + (size_t)ix * D);
        float s0 = 0.f, s1 = 0.f, s2 = 0.f, s3 = 0.f;
        #pragma unroll 8
        for (int j = 0; j < D / 4; j++) {
            float4 bv = rp[j];
            float4 av = sh_a4[j];
            s0 += fabsf(av.x - bv.x);
            s1 += fabsf(av.y - bv.y);
            s2 += fabsf(av.z - bv.z);
            s3 += fabsf(av.w - bv.w);
        }
        sh_dv[tid] = (s0 + s1) + (s2 + s3);
    }
    __syncthreads();

    if (tid < 32) {
        // lane holds 5 values (stride 32); nonneg floats order as uint bits.
        float v[5];
        #pragma unroll
        for (int k = 0; k < 5; k++) v[k] = sh_dv[lane + 32 * k];
        const float INF = __int_as_float(0x7f800000);
        float Dm = g_Dm[ai];
        float loss = 0.0f;
        #pragma unroll 1
        for (int it = 0; it < KTOP; it++) {
            uint mb = 0xffffffffu;
            #pragma unroll
            for (int k = 0; k < 5; k++) mb = min(mb, __float_as_uint(v[k]));
            mb = __reduce_min_sync(0xffffffffu, mb);
            float m = __uint_as_float(mb);
            loss += fmaxf(0.0f, Dm - m);
            // remove exactly one copy of m (ballot-elected leader lane)
            bool have = (v[0] == m) | (v[1] == m) | (v[2] == m) |
                        (v[3] == m) | (v[4] == m);
            uint msk = __ballot_sync(0xffffffffu, have);
            if (lane == (int)(__ffs(msk) - 1)) {
                if      (v[0] == m) v[0] = INF;
                else if (v[1] == m) v[1] = INF;
                else if (v[2] == m) v[2] = INF;
                else if (v[3] == m) v[3] = INF;
                else                v[4] = INF;
            }
        }
        if (lane == 0) g_partial[a] = loss;
    }
}

// ---------------------------------------------------------------------------
// Deterministic final reduction: 2048 partials -> scalar / (A*K)
// ---------------------------------------------------------------------------
__global__ void k_final(float* __restrict__ out) {
    __shared__ float s[512];
    int tid = threadIdx.x;   // 1024 threads; 512 float4 elements total
    float v = 0.0f;
    if (tid < 512) {
        float4 p = ((const float4*)g_partial)[tid];
        v = (p.x + p.y) + (p.z + p.w);
        s[tid] = v;
    }
    __syncthreads();
    for (int st = 256; st; st >>= 1) {
        if (tid < st) s[tid] += s[tid + st];
        __syncthreads();
    }
    if (tid == 0) out[0] = s[0] / (float)(NA * KTOP);
}

// ---------------------------------------------------------------------------
extern "C" void kernel_launch(void* const* d_in, const int* in_sizes, int n_in,
                              void* d_out, int out_size) {
    const float* out1 = (const float*)d_in[0];
    const float* out2 = (const float*)d_in[1];
    const int*   an1  = (const int*)d_in[2];
    const int*   an2  = (const int*)d_in[3];
    float* out = (float*)d_out;

    k_prep<<<2 * QB + NA / 2, 256>>>(out1, out2, an1, an2);
    k_dist<<<dim3(NA / TA, NCHUNK, 2), 512>>>();
    k_exact<<<2 * NA, 256>>>(out1, out2);
    k_final<<<1, 1024>>>(out);
}